// round 1
// baseline (speedup 1.0000x reference)
#include <cuda_runtime.h>
#include <cuda_bf16.h>
#include <math.h>

#define BSZ 16
#define CW  32      // width / channels
#define MY  180     // SY
#define NX  360     // SX
#define KM  32      // modes
#define CIN 16

#define PIX (BSZ*MY*NX)           // 1,036,800
#define HSZ (BSZ*CW*MY*NX)        // 33,177,600 floats

// ---------------- device scratch (static globals: allowed) ----------------
__device__ float  g_h  [HSZ];
__device__ float  g_x1 [HSZ];
__device__ float2 g_fty[BSZ*CW*KM*NX];  // [b][i][k][n]
__device__ float2 g_oy [BSZ*CW*KM*NX];  // [b][o][k][n]
__device__ float2 g_ftx[BSZ*CW*KM*MY];  // [b][i][k][m]
__device__ float2 g_ox [BSZ*CW*KM*MY];  // [b][o][k][m]
__device__ float  g_Vyr[KM*MY], g_Vyi[KM*MY];
__device__ float  g_Vxr[KM*NX], g_Vxi[KM*NX];
__device__ float  g_gx[NX], g_gy[MY];

__device__ __forceinline__ float geluf(float x) {
    return 0.5f * x * (1.0f + erff(x * 0.70710678118654752f));
}

// ---------------- precompute: Vandermonde + normalized grid ----------------
__global__ void precomputeKernel(const float* __restrict__ sx,
                                 const float* __restrict__ sy) {
    int t = blockIdx.x * blockDim.x + threadIdx.x;
    int stride = gridDim.x * blockDim.x;
    float x0 = sx[0], xL = sx[NX - 1];
    float y0 = sy[0], yL = sy[MY - 1];
    float invRangeX = 1.0f / (xL - x0);
    float invRangeY = 1.0f / (yL - y0);
    float invSqN = rsqrtf((float)NX);
    float invSqM = rsqrtf((float)MY);
    const float TWO_PI = 6.283185307179586f;

    for (int idx = t; idx < KM * NX; idx += stride) {
        int k = idx / NX, n = idx % NX;
        float p = (sx[n] - x0) * invRangeX;
        float ang = -TWO_PI * (float)k * p;
        float s, c;
        sincosf(ang, &s, &c);
        g_Vxr[idx] = c * invSqN;
        g_Vxi[idx] = s * invSqN;
    }
    for (int idx = t; idx < KM * MY; idx += stride) {
        int k = idx / MY, m = idx % MY;
        float p = (sy[m] - y0) * invRangeY;
        float ang = -TWO_PI * (float)k * p;
        float s, c;
        sincosf(ang, &s, &c);
        g_Vyr[idx] = c * invSqM;
        g_Vyi[idx] = s * invSqM;
    }
    for (int n = t; n < NX; n += stride) g_gx[n] = (sx[n] - x0) / xL;
    for (int m = t; m < MY; m += stride) g_gy[m] = (sy[m] - y0) / yL;
}

// ---------------- fc0: lift [x, gx, gy] (18) -> h [b][c][m][n] ----------------
__global__ void fc0Kernel(const float* __restrict__ xin,
                          const float* __restrict__ w,
                          const float* __restrict__ bias) {
    __shared__ float sw[18 * 32];
    __shared__ float sb[32];
    int tid = threadIdx.x;
    for (int e = tid; e < 18 * 32; e += 256) sw[e] = w[e];
    if (tid < 32) sb[tid] = bias[tid];
    __syncthreads();

    int pix = blockIdx.x * 256 + tid;   // exactly PIX = 4050*256
    int b = pix / (MY * NX);
    int mn = pix % (MY * NX);
    int m = mn / NX, n = mn % NX;

    float acc[32];
#pragma unroll
    for (int c = 0; c < 32; c++) acc[c] = sb[c];

    const float* xp = xin + (size_t)pix * CIN;
#pragma unroll
    for (int j = 0; j < CIN; j++) {
        float xv = xp[j];
#pragma unroll
        for (int c = 0; c < 32; c++) acc[c] = fmaf(xv, sw[j * 32 + c], acc[c]);
    }
    float gxv = g_gx[n], gyv = g_gy[m];
#pragma unroll
    for (int c = 0; c < 32; c++) {
        acc[c] = fmaf(gxv, sw[16 * 32 + c], acc[c]);
        acc[c] = fmaf(gyv, sw[17 * 32 + c], acc[c]);
    }
    size_t base = (size_t)b * CW * MY * NX + (size_t)mn;
#pragma unroll
    for (int c = 0; c < 32; c++) g_h[base + (size_t)c * (MY * NX)] = acc[c];
}

// ---------------- fty[b][i][k][n] = sum_m h[b][i][m][n] * Vy[k][m] ----------------
// grid (6 n-tiles, B*CW), block (64,4). Each thread: 1 n, 8 k values.
__global__ void ftyKernel() {
    int bi = blockIdx.y;
    int n0 = blockIdx.x * 64;
    int tx = threadIdx.x, ty = threadIdx.y;
    int tid = ty * 64 + tx;
    int n = n0 + tx;
    bool nvalid = (n < NX);

    __shared__ float sH[20][64];
    __shared__ float sVr[KM][20], sVi[KM][20];

    float ar[8], ai[8];
#pragma unroll
    for (int j = 0; j < 8; j++) { ar[j] = 0.f; ai[j] = 0.f; }

    const float* hbase = g_h + (size_t)bi * MY * NX;

    for (int m0 = 0; m0 < MY; m0 += 20) {
        for (int l = tid; l < 20 * 64; l += 256) {
            int mm = l / 64, nn = l % 64;
            int gn = n0 + nn;
            sH[mm][nn] = (gn < NX) ? hbase[(m0 + mm) * NX + gn] : 0.f;
        }
        for (int l = tid; l < KM * 20; l += 256) {
            int k = l / 20, mm = l % 20;
            sVr[k][mm] = g_Vyr[k * MY + m0 + mm];
            sVi[k][mm] = g_Vyi[k * MY + m0 + mm];
        }
        __syncthreads();
#pragma unroll
        for (int mm = 0; mm < 20; mm++) {
            float hv = sH[mm][tx];
#pragma unroll
            for (int j = 0; j < 8; j++) {
                int k = ty * 8 + j;
                ar[j] = fmaf(hv, sVr[k][mm], ar[j]);
                ai[j] = fmaf(hv, sVi[k][mm], ai[j]);
            }
        }
        __syncthreads();
    }
    if (nvalid) {
        float2* out = g_fty + (size_t)bi * KM * NX;
#pragma unroll
        for (int j = 0; j < 8; j++) {
            int k = ty * 8 + j;
            out[k * NX + n] = make_float2(ar[j], ai[j]);
        }
    }
}

// ---------------- ftx[b][i][k][m] = sum_n h[b][i][m][n] * Vx[k][n] ----------------
// grid (6 m-tiles, B*CW), block 256. Thread: tm = tid&31, k = (tid>>5)*4 + {0..3}.
__global__ void ftxKernel() {
    int bi = blockIdx.y;
    int m0 = blockIdx.x * 32;
    int tid = threadIdx.x;
    int tm = tid & 31;
    int tkg = tid >> 5;   // 0..7

    __shared__ float sH[32][65];
    __shared__ float sVr[KM][64], sVi[KM][64];

    float ar[4], ai[4];
#pragma unroll
    for (int j = 0; j < 4; j++) { ar[j] = 0.f; ai[j] = 0.f; }

    const float* hbase = g_h + (size_t)bi * MY * NX;

    for (int n0 = 0; n0 < NX; n0 += 64) {
        for (int l = tid; l < 32 * 64; l += 256) {
            int mm = l / 64, nn = l % 64;
            int gm = m0 + mm, gn = n0 + nn;
            sH[mm][nn] = (gm < MY && gn < NX) ? hbase[gm * NX + gn] : 0.f;
        }
        for (int l = tid; l < KM * 64; l += 256) {
            int k = l / 64, nn = l % 64;
            int gn = n0 + nn;
            sVr[k][nn] = (gn < NX) ? g_Vxr[k * NX + gn] : 0.f;
            sVi[k][nn] = (gn < NX) ? g_Vxi[k * NX + gn] : 0.f;
        }
        __syncthreads();
#pragma unroll 8
        for (int nn = 0; nn < 64; nn++) {
            float hv = sH[tm][nn];
#pragma unroll
            for (int j = 0; j < 4; j++) {
                int k = tkg * 4 + j;
                ar[j] = fmaf(hv, sVr[k][nn], ar[j]);
                ai[j] = fmaf(hv, sVi[k][nn], ai[j]);
            }
        }
        __syncthreads();
    }
    int m = m0 + tm;
    if (m < MY) {
        float2* out = g_ftx + (size_t)bi * KM * MY;
#pragma unroll
        for (int j = 0; j < 4; j++) {
            int k = tkg * 4 + j;
            out[k * MY + m] = make_float2(ar[j], ai[j]);
        }
    }
}

// ---------------- mode mix: out[b][o][k][l] = sum_i in[b][i][k][l] * w[i][o][k] ----------------
// grid (ceil(L/64), KM, BSZ), block (64,4). complex*complex.
__global__ void mixKernel(const float* __restrict__ fw, int isY) {
    const float2* fin = isY ? g_fty : g_ftx;
    float2* fout = isY ? g_oy : g_ox;
    int L = isY ? NX : MY;

    int b = blockIdx.z, k = blockIdx.y;
    int l0 = blockIdx.x * 64;
    int tx = threadIdx.x, ty = threadIdx.y;
    int tid = ty * 64 + tx;
    int l = l0 + tx;
    bool lv = (l < L);

    __shared__ float2 sW[32][32];   // [i][o]
    __shared__ float2 sF[32][64];   // [i][l]

    for (int e = tid; e < 32 * 32; e += 256) {
        int i = e / 32, o = e % 32;
        const float* p = fw + ((size_t)(i * 32 + o) * KM + k) * 2;
        sW[i][o] = make_float2(p[0], p[1]);
    }
    for (int e = tid; e < 32 * 64; e += 256) {
        int i = e / 64, ll = e % 64;
        sF[i][ll] = (l0 + ll < L)
            ? fin[((size_t)(b * CW + i) * KM + k) * L + l0 + ll]
            : make_float2(0.f, 0.f);
    }
    __syncthreads();

    float ar[8], ai[8];
#pragma unroll
    for (int j = 0; j < 8; j++) { ar[j] = 0.f; ai[j] = 0.f; }

#pragma unroll 4
    for (int i = 0; i < 32; i++) {
        float2 f = sF[i][tx];
#pragma unroll
        for (int j = 0; j < 8; j++) {
            float2 w = sW[i][ty * 8 + j];
            ar[j] = fmaf(w.x, f.x, ar[j]);
            ar[j] = fmaf(-w.y, f.y, ar[j]);
            ai[j] = fmaf(w.x, f.y, ai[j]);
            ai[j] = fmaf(w.y, f.x, ai[j]);
        }
    }
    if (lv) {
#pragma unroll
        for (int j = 0; j < 8; j++) {
            int o = ty * 8 + j;
            fout[((size_t)(b * CW + o) * KM + k) * L + l] = make_float2(ar[j], ai[j]);
        }
    }
}

// ---------------- inverse Y: x1[bo][m][n] = sum_k Re(oy[bo][k][n] * conj(Vy[k][m])) ----------------
// grid (6 n-tiles, 6 m-tiles, B*CW), block 256. Thread: tn=tid&31 (n, n+32), tmg=tid>>5 (4 m).
__global__ void invYKernel() {
    int bo = blockIdx.z;
    int m0 = blockIdx.y * 32;
    int n0 = blockIdx.x * 64;
    int tid = threadIdx.x;
    int tn = tid & 31;
    int tmg = tid >> 5;

    __shared__ float  sVr[KM][32], sVi[KM][32]; // [k][m]
    __shared__ float2 sO[KM][64];               // [k][n]

    for (int e = tid; e < KM * 32; e += 256) {
        int k = e / 32, mm = e % 32;
        int gm = m0 + mm;
        sVr[k][mm] = (gm < MY) ? g_Vyr[k * MY + gm] : 0.f;
        sVi[k][mm] = (gm < MY) ? g_Vyi[k * MY + gm] : 0.f;
    }
    for (int e = tid; e < KM * 64; e += 256) {
        int k = e / 64, nn = e % 64;
        int gn = n0 + nn;
        sO[k][nn] = (gn < NX)
            ? g_oy[((size_t)bo * KM + k) * NX + gn]
            : make_float2(0.f, 0.f);
    }
    __syncthreads();

    float accA[4] = {0.f, 0.f, 0.f, 0.f};
    float accB[4] = {0.f, 0.f, 0.f, 0.f};

#pragma unroll 8
    for (int k = 0; k < KM; k++) {
        float2 o0 = sO[k][tn];
        float2 o1 = sO[k][tn + 32];
#pragma unroll
        for (int q = 0; q < 4; q++) {
            float vr = sVr[k][tmg * 4 + q];
            float vi = sVi[k][tmg * 4 + q];
            accA[q] = fmaf(vr, o0.x, accA[q]);
            accA[q] = fmaf(vi, o0.y, accA[q]);
            accB[q] = fmaf(vr, o1.x, accB[q]);
            accB[q] = fmaf(vi, o1.y, accB[q]);
        }
    }
    float* xb = g_x1 + (size_t)bo * MY * NX;
#pragma unroll
    for (int q = 0; q < 4; q++) {
        int m = m0 + tmg * 4 + q;
        if (m < MY) {
            int nA = n0 + tn, nB = n0 + 32 + tn;
            if (nA < NX) xb[m * NX + nA] = accA[q];
            if (nB < NX) xb[m * NX + nB] = accB[q];
        }
    }
}

// ---------------- inverse X: x1[bo][m][n] += sum_k Re(ox[bo][k][m] * conj(Vx[k][n])) ----------------
__global__ void invXKernel() {
    int bo = blockIdx.z;
    int m0 = blockIdx.y * 32;
    int n0 = blockIdx.x * 64;
    int tid = threadIdx.x;
    int tn = tid & 31;
    int tmg = tid >> 5;

    __shared__ float2 sO[KM][32];               // [k][m]
    __shared__ float  sVr[KM][64], sVi[KM][64]; // [k][n]

    for (int e = tid; e < KM * 32; e += 256) {
        int k = e / 32, mm = e % 32;
        int gm = m0 + mm;
        sO[k][mm] = (gm < MY)
            ? g_ox[((size_t)bo * KM + k) * MY + gm]
            : make_float2(0.f, 0.f);
    }
    for (int e = tid; e < KM * 64; e += 256) {
        int k = e / 64, nn = e % 64;
        int gn = n0 + nn;
        sVr[k][nn] = (gn < NX) ? g_Vxr[k * NX + gn] : 0.f;
        sVi[k][nn] = (gn < NX) ? g_Vxi[k * NX + gn] : 0.f;
    }
    __syncthreads();

    float accA[4] = {0.f, 0.f, 0.f, 0.f};
    float accB[4] = {0.f, 0.f, 0.f, 0.f};

#pragma unroll 8
    for (int k = 0; k < KM; k++) {
        float vr0 = sVr[k][tn],      vi0 = sVi[k][tn];
        float vr1 = sVr[k][tn + 32], vi1 = sVi[k][tn + 32];
#pragma unroll
        for (int q = 0; q < 4; q++) {
            float2 o = sO[k][tmg * 4 + q];
            accA[q] = fmaf(o.x, vr0, accA[q]);
            accA[q] = fmaf(o.y, vi0, accA[q]);
            accB[q] = fmaf(o.x, vr1, accB[q]);
            accB[q] = fmaf(o.y, vi1, accB[q]);
        }
    }
    float* xb = g_x1 + (size_t)bo * MY * NX;
#pragma unroll
    for (int q = 0; q < 4; q++) {
        int m = m0 + tmg * 4 + q;
        if (m < MY) {
            int nA = n0 + tn, nB = n0 + 32 + tn;
            if (nA < NX) xb[m * NX + nA] += accA[q];
            if (nB < NX) xb[m * NX + nB] += accB[q];
        }
    }
}

// ---------------- pointwise channel MLP + residual ----------------
// h = [gelu](w2 @ gelu(w1 @ x1 + b1) + b2) + h
__global__ void pointwiseKernel(const float* __restrict__ w1,
                                const float* __restrict__ b1,
                                const float* __restrict__ w2,
                                const float* __restrict__ b2,
                                int applyGelu) {
    __shared__ float sw1[32 * 32], sw2[32 * 32], sb1[32], sb2[32];
    int tid = threadIdx.x;
    for (int e = tid; e < 1024; e += 256) { sw1[e] = w1[e]; sw2[e] = w2[e]; }
    if (tid < 32) { sb1[tid] = b1[tid]; sb2[tid] = b2[tid]; }
    __syncthreads();

    int pix = blockIdx.x * 256 + tid;
    int b = pix / (MY * NX);
    int mn = pix % (MY * NX);
    size_t base = (size_t)b * CW * MY * NX + (size_t)mn;

    float v[32];
#pragma unroll
    for (int c = 0; c < 32; c++) v[c] = g_x1[base + (size_t)c * (MY * NX)];

    float t[32];
#pragma unroll
    for (int o = 0; o < 32; o++) {
        float s = sb1[o];
#pragma unroll
        for (int c = 0; c < 32; c++) s = fmaf(v[c], sw1[o * 32 + c], s);
        t[o] = geluf(s);
    }
#pragma unroll
    for (int o = 0; o < 32; o++) {
        float s = sb2[o];
#pragma unroll
        for (int c = 0; c < 32; c++) s = fmaf(t[c], sw2[o * 32 + c], s);
        if (applyGelu) s = geluf(s);
        size_t idx = base + (size_t)o * (MY * NX);
        g_h[idx] = s + g_h[idx];
    }
}

// ---------------- final head: fc1 (32->128) + gelu + fc2 (128->1) ----------------
__global__ void finalKernel(const float* __restrict__ fc1w,
                            const float* __restrict__ fc1b,
                            const float* __restrict__ fc2w,
                            const float* __restrict__ fc2b,
                            float* __restrict__ out) {
    __shared__ float sw1[32 * 128];
    __shared__ float sb1[128];
    __shared__ float sw2[128];
    int tid = threadIdx.x;
    for (int e = tid; e < 32 * 128; e += 256) sw1[e] = fc1w[e];
    if (tid < 128) { sb1[tid] = fc1b[tid]; sw2[tid] = fc2w[tid]; }
    __syncthreads();

    int pix = blockIdx.x * 256 + tid;
    int b = pix / (MY * NX);
    int mn = pix % (MY * NX);
    size_t base = (size_t)b * CW * MY * NX + (size_t)mn;

    float v[32];
#pragma unroll
    for (int c = 0; c < 32; c++) v[c] = g_h[base + (size_t)c * (MY * NX)];

    float acc = fc2b[0];
#pragma unroll 4
    for (int j = 0; j < 128; j++) {
        float s = sb1[j];
#pragma unroll
        for (int c = 0; c < 32; c++) s = fmaf(v[c], sw1[c * 128 + j], s);
        acc = fmaf(geluf(s), sw2[j], acc);
    }
    out[pix] = acc;
}

// ---------------- launch ----------------
extern "C" void kernel_launch(void* const* d_in, const int* in_sizes, int n_in,
                              void* d_out, int out_size) {
    (void)in_sizes; (void)n_in; (void)out_size;
    const float* x     = (const float*)d_in[0];
    const float* sx    = (const float*)d_in[1];
    const float* sy    = (const float*)d_in[2];
    const float* fc0w  = (const float*)d_in[3];
    const float* fc0b  = (const float*)d_in[4];
    const float* fw1   = (const float*)d_in[5];
    const float* fw2   = (const float*)d_in[6];
    const float* w1    = (const float*)d_in[7];
    const float* b1    = (const float*)d_in[8];
    const float* w2    = (const float*)d_in[9];
    const float* b2    = (const float*)d_in[10];
    const float* fc1w  = (const float*)d_in[11];
    const float* fc1b  = (const float*)d_in[12];
    const float* fc2w  = (const float*)d_in[13];
    const float* fc2b  = (const float*)d_in[14];
    float* out = (float*)d_out;

    precomputeKernel<<<64, 256>>>(sx, sy);
    fc0Kernel<<<PIX / 256, 256>>>(x, fc0w, fc0b);

    for (int blk = 0; blk < 4; blk++) {
        const float* fw1p = fw1 + (size_t)blk * CW * CW * KM * 2;
        const float* fw2p = fw2 + (size_t)blk * CW * CW * KM * 2;
        const float* w1p  = w1 + (size_t)blk * CW * CW;
        const float* b1p  = b1 + (size_t)blk * CW;
        const float* w2p  = w2 + (size_t)blk * CW * CW;
        const float* b2p  = b2 + (size_t)blk * CW;

        // Y direction
        ftyKernel<<<dim3(6, BSZ * CW), dim3(64, 4)>>>();
        mixKernel<<<dim3(6, KM, BSZ), dim3(64, 4)>>>(fw1p, 1);
        invYKernel<<<dim3(6, 6, BSZ * CW), 256>>>();
        // X direction
        ftxKernel<<<dim3(6, BSZ * CW), 256>>>();
        mixKernel<<<dim3(3, KM, BSZ), dim3(64, 4)>>>(fw2p, 0);
        invXKernel<<<dim3(6, 6, BSZ * CW), 256>>>();
        // channel MLP + residual
        pointwiseKernel<<<PIX / 256, 256>>>(w1p, b1p, w2p, b2p, blk < 3 ? 1 : 0);
    }

    finalKernel<<<PIX / 256, 256>>>(fc1w, fc1b, fc2w, fc2b, out);
}